// round 10
// baseline (speedup 1.0000x reference)
#include <cuda_runtime.h>

// SigmoidFlow: B=2048, D=512, NDIM=16
// out[0..B*D) = xnew ; out[B*D..B*D+B) = logdet
//
// R10 = R9 (profiled best: TPB=512, plain __ldg, R2 math -> 5.6 TB/s) with
// ALU overhead stripped: guard-free unrolled loop (D%128==0 specialization),
// strength-reduced pointers (no per-iter 64-bit idx*48 IMAD chains).
// Math: single-rcp cofactor sigmoids; 3-log epilogue.

#define TPB 512

__device__ __forceinline__ float fast_rcp(float v) {
    float r; asm("rcp.approx.f32 %0, %1;" : "=f"(r) : "f"(v)); return r;
}

__device__ __forceinline__ void sf_body(const float4* __restrict__ pp,
                                        const float* __restrict__ xp,
                                        float* __restrict__ op,
                                        int q, float& acc)
{
    const float ONE_MD = 1.0f - 1e-6f;
    const float HALF_D = 0.5e-6f;
    const float LOG1MD = -1.0000005e-6f;

    const float4 av = __ldg(pp);
    const float4 bv = __ldg(pp + 4);
    const float4 wv = __ldg(pp + 8);
    const float  xv = __ldg(xp);

    float a_[4] = {av.x, av.y, av.z, av.w};
    float bb[4] = {bv.x, bv.y, bv.z, bv.w};
    float wl[4] = {wv.x, wv.y, wv.z, wv.w};

    float asp[4], t[4], onet[4], ew[4];
    #pragma unroll
    for (int j = 0; j < 4; ++j) {
        float ea  = __expf(a_[j]);
        asp[j]    = __logf(1.0f + ea);            // softplus
        float pre = fmaf(asp[j], xv, bb[j]);
        t[j]      = __expf(-pre);
        onet[j]   = 1.0f + t[j];
        ew[j]     = __expf(wl[j]);
    }
    // single-rcp cofactor sigmoids: h_j = 1/(1+t_j)
    float p01 = onet[0] * onet[1];
    float p23 = onet[2] * onet[3];
    float iP  = fast_rcp(p01 * p23);
    float h0  = (onet[1] * p23) * iP;
    float h1  = (onet[0] * p23) * iP;
    float h2  = (p01 * onet[3]) * iP;
    float h3  = (p01 * onet[2]) * iP;

    float Wl = (ew[0] + ew[1]) + (ew[2] + ew[3]);
    float Sl = fmaf(ew[3], h3, fmaf(ew[2], h2, fmaf(ew[1], h1, ew[0] * h0)));
    float d0 = (ew[0] * asp[0]) * (t[0] * h0 * h0);
    float d1 = (ew[1] * asp[1]) * (t[1] * h1 * h1);
    float d2 = (ew[2] * asp[2]) * (t[2] * h2 * h2);
    float d3 = (ew[3] * asp[3]) * (t[3] * h3 * h3);
    float Dl = (d0 + d1) + (d2 + d3);

    // reduce the 3 sums across the 4-lane group
    Wl += __shfl_xor_sync(0xffffffffu, Wl, 1);
    Sl += __shfl_xor_sync(0xffffffffu, Sl, 1);
    Dl += __shfl_xor_sync(0xffffffffu, Dl, 1);
    Wl += __shfl_xor_sync(0xffffffffu, Wl, 2);
    Sl += __shfl_xor_sync(0xffffffffu, Sl, 2);
    Dl += __shfl_xor_sync(0xffffffffu, Dl, 2);

    const float hw = HALF_D * Wl;
    const float N1 = fmaf(ONE_MD, Sl, hw);
    const float N2 = fmaf(ONE_MD, Wl - Sl, hw);
    const float l1 = __logf(N1);
    const float l2 = __logf(N2);
    const float l3 = __logf(Dl * Wl);

    if (q == 0) *op = l1 - l2;                    // xnew
    acc += l3 - l1 - l2 + LOG1MD;                 // replicated x4
}

// Requires D % 128 == 0.
__global__ __launch_bounds__(TPB)
void sf_kernel(const float* __restrict__ x,
               const float* __restrict__ logdet_in,
               const float* __restrict__ dsp,
               float* __restrict__ out,
               int B, int D)
{
    const int b    = blockIdx.x;
    const int tid  = threadIdx.x;
    const int lane = tid & 31;
    const int wid  = tid >> 5;                 // 0..15
    const int q    = lane & 3;
    const int e0   = wid * 8 + (lane >> 2);    // 0..127

    __shared__ float s_part[TPB / 32];

    // strength-reduced pointers
    const float*  xp = x   + (long long)b * D + e0;
    const float4* pp = (const float4*)(dsp + ((long long)b * D + e0) * 48) + q;
    float*        op = out + (long long)b * D + e0;

    float acc = 0.0f;

    const int niter = D >> 7;                  // 128 elements per iteration
    #pragma unroll 4
    for (int it = 0; it < niter; ++it) {
        sf_body(pp, xp, op, q, acc);
        pp += 128 * 12;
        xp += 128;
        op += 128;
    }

    // warp + block reduction (each element counted 4x -> scale by 0.25)
    #pragma unroll
    for (int m = 16; m >= 1; m >>= 1)
        acc += __shfl_xor_sync(0xffffffffu, acc, m);
    if (lane == 0) s_part[wid] = acc;
    __syncthreads();

    if (wid == 0) {
        float v = (lane < (TPB / 32)) ? s_part[lane] : 0.0f;
        #pragma unroll
        for (int m = 8; m >= 1; m >>= 1)
            v += __shfl_xor_sync(0xffffffffu, v, m);
        if (lane == 0)
            out[(long long)B * D + b] = 0.25f * v + __ldg(logdet_in + b);
    }
}

// Generic fallback for D not a multiple of 128.
__global__ __launch_bounds__(TPB)
void sf_kernel_gen(const float* __restrict__ x,
                   const float* __restrict__ logdet_in,
                   const float* __restrict__ dsp,
                   float* __restrict__ out,
                   int B, int D)
{
    const int b    = blockIdx.x;
    const int tid  = threadIdx.x;
    const int lane = tid & 31;
    const int wid  = tid >> 5;
    const int q    = lane & 3;
    const int e0   = wid * 8 + (lane >> 2);

    __shared__ float s_part[TPB / 32];
    float acc = 0.0f;

    const int niter = (D + 127) / 128;
    for (int it = 0; it < niter; ++it) {
        const int d = it * 128 + e0;
        if (d < D) {
            const long long idx = (long long)b * D + d;
            sf_body((const float4*)(dsp + idx * 48) + q, x + idx, out + idx, q, acc);
        }
    }

    #pragma unroll
    for (int m = 16; m >= 1; m >>= 1)
        acc += __shfl_xor_sync(0xffffffffu, acc, m);
    if (lane == 0) s_part[wid] = acc;
    __syncthreads();

    if (wid == 0) {
        float v = (lane < (TPB / 32)) ? s_part[lane] : 0.0f;
        #pragma unroll
        for (int m = 8; m >= 1; m >>= 1)
            v += __shfl_xor_sync(0xffffffffu, v, m);
        if (lane == 0)
            out[(long long)B * D + b] = 0.25f * v + __ldg(logdet_in + b);
    }
}

extern "C" void kernel_launch(void* const* d_in, const int* in_sizes, int n_in,
                              void* d_out, int out_size)
{
    const float* x   = (const float*)d_in[0];   // (B, D)
    const float* ld  = (const float*)d_in[1];   // (B,)
    const float* dsp = (const float*)d_in[2];   // (B, D, 48)
    float* out = (float*)d_out;

    const int B = in_sizes[1];
    const int D = in_sizes[0] / B;

    if ((D & 127) == 0)
        sf_kernel<<<B, TPB>>>(x, ld, dsp, out, B, D);
    else
        sf_kernel_gen<<<B, TPB>>>(x, ld, dsp, out, B, D);
}

// round 11
// speedup vs baseline: 1.0828x; 1.0828x over previous
#include <cuda_runtime.h>

// SigmoidFlow: B=2048, D=512, NDIM=16
// out[0..B*D) = xnew ; out[B*D..B*D+B) = logdet
//
// R11 = R9 (profiled best: TPB=512, plain __ldg, R2 math, 48 warps/SM)
// + guard-free strength-reduced loop (R10's ALU trim) with occupancy pinned
// via __launch_bounds__(512,3) (regs capped <=42 -> 3 CTAs/SM; R10 showed
// 44 regs drops to 2 CTAs/SM and costs 5us). No unroll pragma (keeps live
// ranges short). Math: single-rcp cofactor sigmoids, 3-log epilogue.

#define TPB 512

__device__ __forceinline__ float fast_rcp(float v) {
    float r; asm("rcp.approx.f32 %0, %1;" : "=f"(r) : "f"(v)); return r;
}

__device__ __forceinline__ void sf_body(const float4* __restrict__ pp,
                                        const float* __restrict__ xp,
                                        float* __restrict__ op,
                                        int q, float& acc)
{
    const float ONE_MD = 1.0f - 1e-6f;
    const float HALF_D = 0.5e-6f;
    const float LOG1MD = -1.0000005e-6f;

    const float4 av = __ldg(pp);
    const float4 bv = __ldg(pp + 4);
    const float4 wv = __ldg(pp + 8);
    const float  xv = __ldg(xp);

    float a_[4] = {av.x, av.y, av.z, av.w};
    float bb[4] = {bv.x, bv.y, bv.z, bv.w};
    float wl[4] = {wv.x, wv.y, wv.z, wv.w};

    float asp[4], t[4], onet[4], ew[4];
    #pragma unroll
    for (int j = 0; j < 4; ++j) {
        float ea  = __expf(a_[j]);
        asp[j]    = __logf(1.0f + ea);            // softplus
        float pre = fmaf(asp[j], xv, bb[j]);
        t[j]      = __expf(-pre);
        onet[j]   = 1.0f + t[j];
        ew[j]     = __expf(wl[j]);
    }
    // single-rcp cofactor sigmoids: h_j = 1/(1+t_j)
    float p01 = onet[0] * onet[1];
    float p23 = onet[2] * onet[3];
    float iP  = fast_rcp(p01 * p23);
    float h0  = (onet[1] * p23) * iP;
    float h1  = (onet[0] * p23) * iP;
    float h2  = (p01 * onet[3]) * iP;
    float h3  = (p01 * onet[2]) * iP;

    float Wl = (ew[0] + ew[1]) + (ew[2] + ew[3]);
    float Sl = fmaf(ew[3], h3, fmaf(ew[2], h2, fmaf(ew[1], h1, ew[0] * h0)));
    float d0 = (ew[0] * asp[0]) * (t[0] * h0 * h0);
    float d1 = (ew[1] * asp[1]) * (t[1] * h1 * h1);
    float d2 = (ew[2] * asp[2]) * (t[2] * h2 * h2);
    float d3 = (ew[3] * asp[3]) * (t[3] * h3 * h3);
    float Dl = (d0 + d1) + (d2 + d3);

    // reduce the 3 sums across the 4-lane group
    Wl += __shfl_xor_sync(0xffffffffu, Wl, 1);
    Sl += __shfl_xor_sync(0xffffffffu, Sl, 1);
    Dl += __shfl_xor_sync(0xffffffffu, Dl, 1);
    Wl += __shfl_xor_sync(0xffffffffu, Wl, 2);
    Sl += __shfl_xor_sync(0xffffffffu, Sl, 2);
    Dl += __shfl_xor_sync(0xffffffffu, Dl, 2);

    const float hw = HALF_D * Wl;
    const float N1 = fmaf(ONE_MD, Sl, hw);
    const float N2 = fmaf(ONE_MD, Wl - Sl, hw);
    const float l1 = __logf(N1);
    const float l2 = __logf(N2);
    const float l3 = __logf(Dl * Wl);

    if (q == 0) *op = l1 - l2;                    // xnew
    acc += l3 - l1 - l2 + LOG1MD;                 // replicated x4
}

// Requires D % 128 == 0.
__global__ __launch_bounds__(TPB, 3)
void sf_kernel(const float* __restrict__ x,
               const float* __restrict__ logdet_in,
               const float* __restrict__ dsp,
               float* __restrict__ out,
               int B, int D)
{
    const int b    = blockIdx.x;
    const int tid  = threadIdx.x;
    const int lane = tid & 31;
    const int wid  = tid >> 5;                 // 0..15
    const int q    = lane & 3;
    const int e0   = wid * 8 + (lane >> 2);    // 0..127

    __shared__ float s_part[TPB / 32];

    // strength-reduced pointers
    const float*  xp = x   + (long long)b * D + e0;
    const float4* pp = (const float4*)(dsp + ((long long)b * D + e0) * 48) + q;
    float*        op = out + (long long)b * D + e0;

    float acc = 0.0f;

    const int niter = D >> 7;                  // 128 elements per iteration
    for (int it = 0; it < niter; ++it) {
        sf_body(pp, xp, op, q, acc);
        pp += 128 * 12;
        xp += 128;
        op += 128;
    }

    // warp + block reduction (each element counted 4x -> scale by 0.25)
    #pragma unroll
    for (int m = 16; m >= 1; m >>= 1)
        acc += __shfl_xor_sync(0xffffffffu, acc, m);
    if (lane == 0) s_part[wid] = acc;
    __syncthreads();

    if (wid == 0) {
        float v = (lane < (TPB / 32)) ? s_part[lane] : 0.0f;
        #pragma unroll
        for (int m = 8; m >= 1; m >>= 1)
            v += __shfl_xor_sync(0xffffffffu, v, m);
        if (lane == 0)
            out[(long long)B * D + b] = 0.25f * v + __ldg(logdet_in + b);
    }
}

// Generic fallback for D not a multiple of 128.
__global__ __launch_bounds__(TPB)
void sf_kernel_gen(const float* __restrict__ x,
                   const float* __restrict__ logdet_in,
                   const float* __restrict__ dsp,
                   float* __restrict__ out,
                   int B, int D)
{
    const int b    = blockIdx.x;
    const int tid  = threadIdx.x;
    const int lane = tid & 31;
    const int wid  = tid >> 5;
    const int q    = lane & 3;
    const int e0   = wid * 8 + (lane >> 2);

    __shared__ float s_part[TPB / 32];
    float acc = 0.0f;

    const int niter = (D + 127) / 128;
    for (int it = 0; it < niter; ++it) {
        const int d = it * 128 + e0;
        if (d < D) {
            const long long idx = (long long)b * D + d;
            sf_body((const float4*)(dsp + idx * 48) + q, x + idx, out + idx, q, acc);
        }
    }

    #pragma unroll
    for (int m = 16; m >= 1; m >>= 1)
        acc += __shfl_xor_sync(0xffffffffu, acc, m);
    if (lane == 0) s_part[wid] = acc;
    __syncthreads();

    if (wid == 0) {
        float v = (lane < (TPB / 32)) ? s_part[lane] : 0.0f;
        #pragma unroll
        for (int m = 8; m >= 1; m >>= 1)
            v += __shfl_xor_sync(0xffffffffu, v, m);
        if (lane == 0)
            out[(long long)B * D + b] = 0.25f * v + __ldg(logdet_in + b);
    }
}

extern "C" void kernel_launch(void* const* d_in, const int* in_sizes, int n_in,
                              void* d_out, int out_size)
{
    const float* x   = (const float*)d_in[0];   // (B, D)
    const float* ld  = (const float*)d_in[1];   // (B,)
    const float* dsp = (const float*)d_in[2];   // (B, D, 48)
    float* out = (float*)d_out;

    const int B = in_sizes[1];
    const int D = in_sizes[0] / B;

    if ((D & 127) == 0)
        sf_kernel<<<B, TPB>>>(x, ld, dsp, out, B, D);
    else
        sf_kernel_gen<<<B, TPB>>>(x, ld, dsp, out, B, D);
}

// round 12
// speedup vs baseline: 1.1039x; 1.0195x over previous
#include <cuda_runtime.h>

// SigmoidFlow: B=2048, D=512, NDIM=16
// out[0..B*D) = xnew ; out[B*D..B*D+B) = logdet
//
// R12: high-MLP x high-warp-count combination (never tested together).
// TPB=256, one row/CTA, 2-chunk interleaved body: both chunks' loads issued
// back-to-back (6 LDG.128 + 2 LDG.32 in flight = 3 KB/warp), then compute
// both. __launch_bounds__(256,5) caps regs at 51 -> 5 CTAs/SM = 40 warps.
// Math: R2 single-rcp cofactor sigmoids, 3-log epilogue.

#define TPB 256

__device__ __forceinline__ float fast_rcp(float v) {
    float r; asm("rcp.approx.f32 %0, %1;" : "=f"(r) : "f"(v)); return r;
}

__device__ __forceinline__ void sf_math(float4 av, float4 bv, float4 wv, float xv,
                                        int q, float* __restrict__ op, float& acc)
{
    const float ONE_MD = 1.0f - 1e-6f;
    const float HALF_D = 0.5e-6f;
    const float LOG1MD = -1.0000005e-6f;

    float a_[4] = {av.x, av.y, av.z, av.w};
    float bb[4] = {bv.x, bv.y, bv.z, bv.w};
    float wl[4] = {wv.x, wv.y, wv.z, wv.w};

    float asp[4], t[4], onet[4], ew[4];
    #pragma unroll
    for (int j = 0; j < 4; ++j) {
        float ea  = __expf(a_[j]);
        asp[j]    = __logf(1.0f + ea);            // softplus
        float pre = fmaf(asp[j], xv, bb[j]);
        t[j]      = __expf(-pre);
        onet[j]   = 1.0f + t[j];
        ew[j]     = __expf(wl[j]);
    }
    float p01 = onet[0] * onet[1];
    float p23 = onet[2] * onet[3];
    float iP  = fast_rcp(p01 * p23);
    float h0  = (onet[1] * p23) * iP;
    float h1  = (onet[0] * p23) * iP;
    float h2  = (p01 * onet[3]) * iP;
    float h3  = (p01 * onet[2]) * iP;

    float Wl = (ew[0] + ew[1]) + (ew[2] + ew[3]);
    float Sl = fmaf(ew[3], h3, fmaf(ew[2], h2, fmaf(ew[1], h1, ew[0] * h0)));
    float d0 = (ew[0] * asp[0]) * (t[0] * h0 * h0);
    float d1 = (ew[1] * asp[1]) * (t[1] * h1 * h1);
    float d2 = (ew[2] * asp[2]) * (t[2] * h2 * h2);
    float d3 = (ew[3] * asp[3]) * (t[3] * h3 * h3);
    float Dl = (d0 + d1) + (d2 + d3);

    Wl += __shfl_xor_sync(0xffffffffu, Wl, 1);
    Sl += __shfl_xor_sync(0xffffffffu, Sl, 1);
    Dl += __shfl_xor_sync(0xffffffffu, Dl, 1);
    Wl += __shfl_xor_sync(0xffffffffu, Wl, 2);
    Sl += __shfl_xor_sync(0xffffffffu, Sl, 2);
    Dl += __shfl_xor_sync(0xffffffffu, Dl, 2);

    const float hw = HALF_D * Wl;
    const float N1 = fmaf(ONE_MD, Sl, hw);
    const float N2 = fmaf(ONE_MD, Wl - Sl, hw);
    const float l1 = __logf(N1);
    const float l2 = __logf(N2);
    const float l3 = __logf(Dl * Wl);

    if (q == 0) *op = l1 - l2;                    // xnew
    acc += l3 - l1 - l2 + LOG1MD;                 // replicated x4
}

// Requires D % 128 == 0.
__global__ __launch_bounds__(TPB, 5)
void sf_kernel(const float* __restrict__ x,
               const float* __restrict__ logdet_in,
               const float* __restrict__ dsp,
               float* __restrict__ out,
               int B, int D)
{
    const int b    = blockIdx.x;
    const int tid  = threadIdx.x;
    const int lane = tid & 31;
    const int wid  = tid >> 5;                 // 0..7
    const int q    = lane & 3;
    const int e0   = wid * 8 + (lane >> 2);    // 0..63

    __shared__ float s_part[TPB / 32];

    const float*  xp = x   + (long long)b * D + e0;
    const float4* pp = (const float4*)(dsp + ((long long)b * D + e0) * 48) + q;
    float*        op = out + (long long)b * D + e0;

    float acc = 0.0f;

    const int niter = D >> 7;                  // 128 elements (2 chunks) per iter
    for (int it = 0; it < niter; ++it) {
        // ---- issue ALL loads for both chunks first (MLP = 6x LDG.128 + 2) ----
        const float4 av0 = __ldg(pp);
        const float4 bv0 = __ldg(pp + 4);
        const float4 wv0 = __ldg(pp + 8);
        const float4 av1 = __ldg(pp + 64 * 12);
        const float4 bv1 = __ldg(pp + 64 * 12 + 4);
        const float4 wv1 = __ldg(pp + 64 * 12 + 8);
        const float  xv0 = __ldg(xp);
        const float  xv1 = __ldg(xp + 64);

        // ---- compute both chunks ----
        sf_math(av0, bv0, wv0, xv0, q, op, acc);
        sf_math(av1, bv1, wv1, xv1, q, op + 64, acc);

        pp += 128 * 12;
        xp += 128;
        op += 128;
    }

    // warp + block reduction (each element counted 4x -> scale 0.25)
    #pragma unroll
    for (int m = 16; m >= 1; m >>= 1)
        acc += __shfl_xor_sync(0xffffffffu, acc, m);
    if (lane == 0) s_part[wid] = acc;
    __syncthreads();

    if (wid == 0) {
        float v = (lane < (TPB / 32)) ? s_part[lane] : 0.0f;
        #pragma unroll
        for (int m = 4; m >= 1; m >>= 1)
            v += __shfl_xor_sync(0xffffffffu, v, m);
        if (lane == 0)
            out[(long long)B * D + b] = 0.25f * v + __ldg(logdet_in + b);
    }
}

// Generic fallback for D not a multiple of 128.
__global__ __launch_bounds__(TPB)
void sf_kernel_gen(const float* __restrict__ x,
                   const float* __restrict__ logdet_in,
                   const float* __restrict__ dsp,
                   float* __restrict__ out,
                   int B, int D)
{
    const int b    = blockIdx.x;
    const int tid  = threadIdx.x;
    const int lane = tid & 31;
    const int wid  = tid >> 5;
    const int q    = lane & 3;
    const int e0   = wid * 8 + (lane >> 2);

    __shared__ float s_part[TPB / 32];
    float acc = 0.0f;

    const int niter = (D + 63) / 64;
    for (int it = 0; it < niter; ++it) {
        const int d = it * 64 + e0;
        if (d < D) {
            const long long idx = (long long)b * D + d;
            const float4* p = (const float4*)(dsp + idx * 48);
            sf_math(__ldg(p + q), __ldg(p + 4 + q), __ldg(p + 8 + q),
                    __ldg(x + idx), q, out + idx, acc);
        }
    }

    #pragma unroll
    for (int m = 16; m >= 1; m >>= 1)
        acc += __shfl_xor_sync(0xffffffffu, acc, m);
    if (lane == 0) s_part[wid] = acc;
    __syncthreads();

    if (wid == 0) {
        float v = (lane < (TPB / 32)) ? s_part[lane] : 0.0f;
        #pragma unroll
        for (int m = 4; m >= 1; m >>= 1)
            v += __shfl_xor_sync(0xffffffffu, v, m);
        if (lane == 0)
            out[(long long)B * D + b] = 0.25f * v + __ldg(logdet_in + b);
    }
}

extern "C" void kernel_launch(void* const* d_in, const int* in_sizes, int n_in,
                              void* d_out, int out_size)
{
    const float* x   = (const float*)d_in[0];   // (B, D)
    const float* ld  = (const float*)d_in[1];   // (B,)
    const float* dsp = (const float*)d_in[2];   // (B, D, 48)
    float* out = (float*)d_out;

    const int B = in_sizes[1];
    const int D = in_sizes[0] / B;

    if ((D & 127) == 0)
        sf_kernel<<<B, TPB>>>(x, ld, dsp, out, B, D);
    else
        sf_kernel_gen<<<B, TPB>>>(x, ld, dsp, out, B, D);
}